// round 6
// baseline (speedup 1.0000x reference)
#include <cuda_runtime.h>

#define BB 512
#define LL 2048
#define CC 64
#define START_S 62
#define STOP_S 63

// scratch (no cudaMalloc allowed)
__device__ float2 g_eTp[CC * 32];   // [cp][k2] = { exp(T[2k2][cp]), exp(T[2k2+1][cp]) }
__device__ float g_eTstop[CC];      // exp(T[c][STOP])
__device__ float g_trow_start[CC];  // T[START][c]
__device__ float g_part[BB];
__device__ float g_scores[BB];

typedef unsigned long long u64;

// packed fp32x2 ops (sm_100+ PTX only; ptxas never emits these from C++)
__device__ __forceinline__ u64 fma2(u64 a, u64 b, u64 c) {
    u64 d;
    asm("fma.rn.f32x2 %0, %1, %2, %3;" : "=l"(d) : "l"(a), "l"(b), "l"(c));
    return d;
}
__device__ __forceinline__ u64 fadd2(u64 a, u64 b) {
    u64 d;
    asm("add.rn.f32x2 %0, %1, %2;" : "=l"(d) : "l"(a), "l"(b));
    return d;
}
__device__ __forceinline__ float sum2(u64 a) {
    float lo, hi;
    asm("mov.b64 {%0,%1}, %2;" : "=f"(lo), "=f"(hi) : "l"(a));
    return lo + hi;
}

// ---------------------------------------------------------------------------
// Precompute packed exp(T) + boundary vectors.
// ---------------------------------------------------------------------------
__global__ void prep_kernel(const float* __restrict__ T) {
    int i = blockIdx.x * blockDim.x + threadIdx.x;
    if (i < CC * 32) {
        int cp = i >> 5;
        int k2 = i & 31;
        g_eTp[i] = make_float2(__expf(T[(2 * k2) * CC + cp]),
                               __expf(T[(2 * k2 + 1) * CC + cp]));
    }
    if (i < CC) {
        g_eTstop[i]     = __expf(T[i * CC + STOP_S]);
        g_trow_start[i] = T[START_S * CC + i];
    }
}

// 32-wide half-dot in packed fp32x2: 16 fma2, 4 chains of depth 4
__device__ __forceinline__ float dot32p(const float* __restrict__ vp,
                                        const u64* __restrict__ eT) {
    const ulonglong2* q = reinterpret_cast<const ulonglong2*>(vp);
    u64 a0 = 0, a1 = 0, a2 = 0, a3 = 0;   // 0x0 == packed {0.f,0.f}
#pragma unroll
    for (int j = 0; j < 8; j += 2) {
        ulonglong2 x = q[j];
        ulonglong2 y = q[j + 1];
        a0 = fma2(x.x, eT[2 * j + 0], a0);
        a1 = fma2(x.y, eT[2 * j + 1], a1);
        a2 = fma2(y.x, eT[2 * j + 2], a2);
        a3 = fma2(y.y, eT[2 * j + 3], a3);
    }
    return sum2(fadd2(fadd2(a0, a1), fadd2(a2, a3)));
}

// one forward step. MODE: 0 plain, 1 launch warp-max of v, 2 apply renorm.
template <int MODE>
__device__ __forceinline__ void do_step(float emv, float mkv,
                                        float& v, float& S,
                                        int& cur, float (*vsh)[CC],
                                        float* smaxb,
                                        int h, int cp, int lane, int wid,
                                        const u64* __restrict__ eT) {
    if (MODE == 1) {            // warp-max of current v — overlaps the dot
        float x = v;
#pragma unroll
        for (int o = 16; o; o >>= 1) x = fmaxf(x, __shfl_xor_sync(0xffffffffu, x, o));
        if (lane == 0) smaxb[wid] = x;
    }
    float ee = __expf(emv);
    float vr = v;
    if (MODE == 2) {            // fold r = 1/max into emission factor
        float m = fmaxf(fmaxf(smaxb[0], smaxb[1]), fmaxf(smaxb[2], smaxb[3]));
        float r = __fdividef(1.0f, m);
        S += __logf(m);
        ee *= r;
        vr = v * r;
    }
    float a = dot32p(vsh[cur] + 32 * h, eT);
    a += __shfl_xor_sync(0xffffffffu, a, 1);
    float nv = (mkv > 0.f) ? a * ee : vr;
    v = nv;
    if (h == 0) vsh[cur ^ 1][cp] = nv;
    __syncthreads();
    cur ^= 1;
}

// ---------------------------------------------------------------------------
// Forward algorithm in exp-space. One block (128 threads) per batch.
// Thread (2*cp + h) computes half h of the 64-dot for output state cp
// (split-K=2) in packed fp32x2 (16 fma2 = 32 MACs), combined by shfl_xor(1).
// Renormalization every 4 steps (growth <= e^24 per window, safe in fp32):
//   step 4k+1: launch warp-max shuffles (overlapping the dot)
//   step 4k+2: fold r = 1/max into the emission factor, S += log(max)
// Invariant: alpha[c] = log(v[c]) + S.
// ---------------------------------------------------------------------------
__global__ void __launch_bounds__(128) alpha_kernel(const float* __restrict__ em,
                                                    const float* __restrict__ mask) {
    const int b    = blockIdx.x;
    const int tid  = threadIdx.x;
    const int h    = tid & 1;
    const int cp   = tid >> 1;
    const int lane = tid & 31;
    const int wid  = tid >> 5;

    __shared__ __align__(16) float vsh[2][CC];
    __shared__ float smaxb[4];
    __shared__ float ssum[4];

    // my 16 packed exp(T) coefficients: g_eTp[cp*32 + 16h ...]
    u64 eT[16];
    {
        const u64* g = reinterpret_cast<const u64*>(g_eTp) + (cp * 32 + 16 * h);
#pragma unroll
        for (int k = 0; k < 16; ++k) eT[k] = g[k];
    }

    const float* emb = em + (size_t)b * (LL * CC);
    const float* mkb = mask + (size_t)b * LL;

    // t = 0
    float v = __expf(emb[cp] + g_trow_start[cp]);
    float S = 0.0f;
    if (h == 0) vsh[0][cp] = v;

    // prefetch pipeline, distance 3
    float ea = emb[1 * CC + cp], ma = mkb[1];
    float eb = emb[2 * CC + cp], mb = mkb[2];
    float ec = emb[3 * CC + cp], mc = mkb[3];

    __syncthreads();

    int cur = 0;
    // advance pipeline for the step just consumed (step index t)
#define ADVANCE(t_)                                                     \
    {                                                                   \
        int ti = (t_) + 3; if (ti > LL - 1) ti = LL - 1;                \
        float en = emb[(size_t)ti * CC + cp];                           \
        float mn = mkb[ti];                                             \
        ea = eb; ma = mb; eb = ec; mb = mc; ec = en; mc = mn;           \
    }

#pragma unroll 1
    for (int t = 1; t <= LL - 4; t += 4) {
        float e0 = ea, m0 = ma; ADVANCE(t);
        do_step<1>(e0, m0, v, S, cur, vsh, smaxb, h, cp, lane, wid, eT);
        float e1 = ea, m1 = ma; ADVANCE(t + 1);
        do_step<2>(e1, m1, v, S, cur, vsh, smaxb, h, cp, lane, wid, eT);
        float e2 = ea, m2 = ma; ADVANCE(t + 2);
        do_step<0>(e2, m2, v, S, cur, vsh, smaxb, h, cp, lane, wid, eT);
        float e3 = ea, m3 = ma; ADVANCE(t + 3);
        do_step<0>(e3, m3, v, S, cur, vsh, smaxb, h, cp, lane, wid, eT);
    }
    // tail: t = 2045, 2046, 2047 (LL-1 = 2047 total steps; 511*4 = 2044 done)
#pragma unroll 1
    for (int t = LL - 3; t < LL; ++t) {
        float e0 = ea, m0 = ma; ADVANCE(t);
        do_step<0>(e0, m0, v, S, cur, vsh, smaxb, h, cp, lane, wid, eT);
    }
#undef ADVANCE

    // partition_b = log( sum_c v[c] * exp(T[c,STOP]) ) + S  (count each c once)
    float term = (h == 0) ? v * g_eTstop[cp] : 0.0f;
#pragma unroll
    for (int o = 16; o; o >>= 1) term += __shfl_xor_sync(0xffffffffu, term, o);
    if (lane == 0) ssum[wid] = term;
    __syncthreads();
    if (tid == 0)
        g_part[b] = __logf((ssum[0] + ssum[1]) + (ssum[2] + ssum[3])) + S;
}

// ---------------------------------------------------------------------------
// Gold path score per batch (cheap gathers).
// ---------------------------------------------------------------------------
__global__ void __launch_bounds__(256) scores_kernel(const float* __restrict__ em,
                                                     const float* __restrict__ T,
                                                     const float* __restrict__ mask,
                                                     const int* __restrict__ tags) {
    const int b   = blockIdx.x;
    const int tid = threadIdx.x;
    const float* emb = em + (size_t)b * (LL * CC);
    const float* mkb = mask + (size_t)b * LL;
    const int*   tgb = tags + (size_t)b * LL;

    float acc = 0.f, msum = 0.f;
    for (int t = tid; t < LL; t += 256) {
        msum += mkb[t];
        if (t >= 1) {
            int tg = tgb[t];
            int tq = tgb[t - 1];
            acc += (emb[(size_t)t * CC + tg] + T[tq * CC + tg]) * mkb[t];
        }
    }

    __shared__ float sacc[8], smsum[8];
#pragma unroll
    for (int o = 16; o; o >>= 1) {
        acc  += __shfl_xor_sync(0xffffffffu, acc, o);
        msum += __shfl_xor_sync(0xffffffffu, msum, o);
    }
    int lane = tid & 31, w = tid >> 5;
    if (lane == 0) { sacc[w] = acc; smsum[w] = msum; }
    __syncthreads();
    if (tid == 0) {
        float A = 0.f, M = 0.f;
#pragma unroll
        for (int i = 0; i < 8; ++i) { A += sacc[i]; M += smsum[i]; }
        int t0 = tgb[0];
        float s = A + emb[t0] + T[START_S * CC + t0];
        int last = (int)M - 1;               // mask sum of 1.0s is exact in fp32
        s += T[tgb[last] * CC + STOP_S];
        g_scores[b] = s;
    }
}

// ---------------------------------------------------------------------------
// mean(partition - scores)
// ---------------------------------------------------------------------------
__global__ void __launch_bounds__(512) finalize_kernel(float* __restrict__ out) {
    int tid = threadIdx.x;
    float d = g_part[tid] - g_scores[tid];
    __shared__ float sh[16];
#pragma unroll
    for (int o = 16; o; o >>= 1) d += __shfl_xor_sync(0xffffffffu, d, o);
    if ((tid & 31) == 0) sh[tid >> 5] = d;
    __syncthreads();
    if (tid < 16) {
        float x = sh[tid];
#pragma unroll
        for (int o = 8; o; o >>= 1) x += __shfl_xor_sync(0x0000ffffu, x, o);
        if (tid == 0) out[0] = x * (1.0f / BB);
    }
}

extern "C" void kernel_launch(void* const* d_in, const int* in_sizes, int n_in,
                              void* d_out, int out_size) {
    (void)in_sizes; (void)n_in; (void)out_size;
    const float* em   = (const float*)d_in[0];
    const float* T    = (const float*)d_in[1];
    const float* mask = (const float*)d_in[2];
    const int*   tags = (const int*)d_in[3];
    float* out = (float*)d_out;

    prep_kernel<<<4, 512>>>(T);
    alpha_kernel<<<BB, 128>>>(em, mask);
    scores_kernel<<<BB, 256>>>(em, T, mask, tags);
    finalize_kernel<<<1, 512>>>(out);
}

// round 7
// speedup vs baseline: 1.3387x; 1.3387x over previous
#include <cuda_runtime.h>
#include <cuda_bf16.h>

#define BB 512
#define LL 2048
#define CC 64
#define START_S 62
#define STOP_S 63

// scratch (no cudaMalloc allowed)
__device__ unsigned g_eTbf[CC * 32];  // [cp][k2] = bf16x2{ exp(T[2k2][cp]), exp(T[2k2+1][cp]) }
__device__ float g_eTstop[CC];        // exp(T[c][STOP])
__device__ float g_trow_start[CC];    // T[START][c]
__device__ float g_part[BB];
__device__ float g_scores[BB];

// bf16x2 packed ops
__device__ __forceinline__ unsigned bffma(unsigned a, unsigned b, unsigned c) {
    unsigned d;
    asm("fma.rn.bf16x2 %0, %1, %2, %3;" : "=r"(d) : "r"(a), "r"(b), "r"(c));
    return d;
}
__device__ __forceinline__ unsigned bfadd(unsigned a, unsigned b) {
    unsigned d;
    asm("add.rn.bf16x2 %0, %1, %2;" : "=r"(d) : "r"(a), "r"(b));
    return d;
}
// sum both bf16 lanes into fp32 (bf16 -> fp32 is a 16-bit shift)
__device__ __forceinline__ float bfsum(unsigned ab) {
    float lo = __uint_as_float(ab << 16);
    float hi = __uint_as_float(ab & 0xffff0000u);
    return lo + hi;
}

// ---------------------------------------------------------------------------
// Precompute bf16x2-packed exp(T) + fp32 boundary vectors.
// ---------------------------------------------------------------------------
__global__ void prep_kernel(const float* __restrict__ T) {
    int i = blockIdx.x * blockDim.x + threadIdx.x;
    if (i < CC * 32) {
        int cp = i >> 5;
        int k2 = i & 31;
        __nv_bfloat162 p = __floats2bfloat162_rn(__expf(T[(2 * k2) * CC + cp]),
                                                 __expf(T[(2 * k2 + 1) * CC + cp]));
        g_eTbf[i] = *reinterpret_cast<unsigned*>(&p);
    }
    if (i < CC) {
        g_eTstop[i]     = __expf(T[i * CC + STOP_S]);
        g_trow_start[i] = T[START_S * CC + i];
    }
}

// 64-dot in bf16x2: 32 HFMA2 into 8 accumulators (depth 4), fp32 result
__device__ __forceinline__ float dotbf(const unsigned* __restrict__ vsh32,
                                       const unsigned* __restrict__ eT) {
    const uint4* q = reinterpret_cast<const uint4*>(vsh32);
    unsigned a0 = 0, a1 = 0, a2 = 0, a3 = 0, a4 = 0, a5 = 0, a6 = 0, a7 = 0;
#pragma unroll
    for (int j = 0; j < 8; j += 2) {
        uint4 x = q[j];
        uint4 y = q[j + 1];
        a0 = bffma(x.x, eT[4 * j + 0], a0);
        a1 = bffma(x.y, eT[4 * j + 1], a1);
        a2 = bffma(x.z, eT[4 * j + 2], a2);
        a3 = bffma(x.w, eT[4 * j + 3], a3);
        a4 = bffma(y.x, eT[4 * j + 4], a4);
        a5 = bffma(y.y, eT[4 * j + 5], a5);
        a6 = bffma(y.z, eT[4 * j + 6], a6);
        a7 = bffma(y.w, eT[4 * j + 7], a7);
    }
    unsigned s = bfadd(bfadd(bfadd(a0, a1), bfadd(a2, a3)),
                       bfadd(bfadd(a4, a5), bfadd(a6, a7)));
    return bfsum(s);
}

// one forward step. MODE: 0 plain, 1 launch warp-max of v, 2 apply renorm.
template <int MODE>
__device__ __forceinline__ void do_step(float emv, float mkv,
                                        float& v, float& S,
                                        int& cur, unsigned (*vsh)[32],
                                        float* smaxb,
                                        int cp, int lane, int wid,
                                        const unsigned* __restrict__ eT) {
    if (MODE == 1) {            // warp-max of current v — overlaps the dot
        float x = v;
#pragma unroll
        for (int o = 16; o; o >>= 1) x = fmaxf(x, __shfl_xor_sync(0xffffffffu, x, o));
        if (lane == 0) smaxb[wid] = x;
    }
    float ee = __expf(emv);
    float vr = v;
    if (MODE == 2) {            // fold r = 1/max into emission factor
        float m = fmaxf(smaxb[0], smaxb[1]);
        float r = __fdividef(1.0f, m);
        S += __logf(m);
        ee *= r;
        vr = v * r;
    }
    float a  = dotbf(vsh[cur], eT);
    float nv = (mkv > 0.f) ? a * ee : vr;
    v = nv;
    reinterpret_cast<__nv_bfloat16*>(vsh[cur ^ 1])[cp] = __float2bfloat16_rn(nv);
    __syncthreads();
    cur ^= 1;
}

// ---------------------------------------------------------------------------
// Forward algorithm in exp-space, bf16 tensor-free matvec.
// One block (64 threads, 2 warps) per batch; thread cp = output state.
// exp(T) column packed bf16x2 in 32 registers; v exchanged as a 128-byte
// bf16x2 shared buffer (8 broadcast LDS.128 per thread); all scaling /
// renormalization bookkeeping in fp32. Renorm every 4 steps, pipelined:
//   step 4k+1: launch warp-max shuffles (overlapping the dot)
//   step 4k+2: fold r = 1/max into the emission factor, S += log(max)
// Invariant: alpha[c] = log(v[c]) + S.
// ---------------------------------------------------------------------------
__global__ void __launch_bounds__(CC) alpha_kernel(const float* __restrict__ em,
                                                   const float* __restrict__ mask) {
    const int b    = blockIdx.x;
    const int cp   = threadIdx.x;
    const int lane = cp & 31;
    const int wid  = cp >> 5;

    __shared__ __align__(16) unsigned vsh[2][32];   // bf16x2 state pairs
    __shared__ float smaxb[2];
    __shared__ float ssum[2];

    // my packed exp(T) column: 32 bf16x2 regs
    unsigned eT[32];
    {
        const unsigned* g = g_eTbf + cp * 32;
#pragma unroll
        for (int k = 0; k < 32; ++k) eT[k] = g[k];
    }

    const float* emb = em + (size_t)b * (LL * CC);
    const float* mkb = mask + (size_t)b * LL;

    // t = 0
    float v = __expf(emb[cp] + g_trow_start[cp]);
    float S = 0.0f;
    reinterpret_cast<__nv_bfloat16*>(vsh[0])[cp] = __float2bfloat16_rn(v);

    // prefetch pipeline, distance 3
    float ea = emb[1 * CC + cp], ma = mkb[1];
    float eb = emb[2 * CC + cp], mb = mkb[2];
    float ec = emb[3 * CC + cp], mc = mkb[3];

    __syncthreads();

    int cur = 0;
#define ADVANCE(t_)                                                     \
    {                                                                   \
        int ti = (t_) + 3; if (ti > LL - 1) ti = LL - 1;                \
        float en = emb[(size_t)ti * CC + cp];                           \
        float mn = mkb[ti];                                             \
        ea = eb; ma = mb; eb = ec; mb = mc; ec = en; mc = mn;           \
    }

#pragma unroll 1
    for (int t = 1; t <= LL - 4; t += 4) {
        float e0 = ea, m0 = ma; ADVANCE(t);
        do_step<1>(e0, m0, v, S, cur, vsh, smaxb, cp, lane, wid, eT);
        float e1 = ea, m1 = ma; ADVANCE(t + 1);
        do_step<2>(e1, m1, v, S, cur, vsh, smaxb, cp, lane, wid, eT);
        float e2 = ea, m2 = ma; ADVANCE(t + 2);
        do_step<0>(e2, m2, v, S, cur, vsh, smaxb, cp, lane, wid, eT);
        float e3 = ea, m3 = ma; ADVANCE(t + 3);
        do_step<0>(e3, m3, v, S, cur, vsh, smaxb, cp, lane, wid, eT);
    }
    // tail: t = 2045, 2046, 2047
#pragma unroll 1
    for (int t = LL - 3; t < LL; ++t) {
        float e0 = ea, m0 = ma; ADVANCE(t);
        do_step<0>(e0, m0, v, S, cur, vsh, smaxb, cp, lane, wid, eT);
    }
#undef ADVANCE

    // partition_b = log( sum_c v[c] * exp(T[c,STOP]) ) + S   (fp32)
    float term = v * g_eTstop[cp];
#pragma unroll
    for (int o = 16; o; o >>= 1) term += __shfl_xor_sync(0xffffffffu, term, o);
    if (lane == 0) ssum[wid] = term;
    __syncthreads();
    if (cp == 0) g_part[b] = __logf(ssum[0] + ssum[1]) + S;
}

// ---------------------------------------------------------------------------
// Gold path score per batch (cheap gathers) — exact fp32.
// ---------------------------------------------------------------------------
__global__ void __launch_bounds__(256) scores_kernel(const float* __restrict__ em,
                                                     const float* __restrict__ T,
                                                     const float* __restrict__ mask,
                                                     const int* __restrict__ tags) {
    const int b   = blockIdx.x;
    const int tid = threadIdx.x;
    const float* emb = em + (size_t)b * (LL * CC);
    const float* mkb = mask + (size_t)b * LL;
    const int*   tgb = tags + (size_t)b * LL;

    float acc = 0.f, msum = 0.f;
    for (int t = tid; t < LL; t += 256) {
        msum += mkb[t];
        if (t >= 1) {
            int tg = tgb[t];
            int tq = tgb[t - 1];
            acc += (emb[(size_t)t * CC + tg] + T[tq * CC + tg]) * mkb[t];
        }
    }

    __shared__ float sacc[8], smsum[8];
#pragma unroll
    for (int o = 16; o; o >>= 1) {
        acc  += __shfl_xor_sync(0xffffffffu, acc, o);
        msum += __shfl_xor_sync(0xffffffffu, msum, o);
    }
    int lane = tid & 31, w = tid >> 5;
    if (lane == 0) { sacc[w] = acc; smsum[w] = msum; }
    __syncthreads();
    if (tid == 0) {
        float A = 0.f, M = 0.f;
#pragma unroll
        for (int i = 0; i < 8; ++i) { A += sacc[i]; M += smsum[i]; }
        int t0 = tgb[0];
        float s = A + emb[t0] + T[START_S * CC + t0];
        int last = (int)M - 1;               // mask sum of 1.0s is exact in fp32
        s += T[tgb[last] * CC + STOP_S];
        g_scores[b] = s;
    }
}

// ---------------------------------------------------------------------------
// mean(partition - scores)
// ---------------------------------------------------------------------------
__global__ void __launch_bounds__(512) finalize_kernel(float* __restrict__ out) {
    int tid = threadIdx.x;
    float d = g_part[tid] - g_scores[tid];
    __shared__ float sh[16];
#pragma unroll
    for (int o = 16; o; o >>= 1) d += __shfl_xor_sync(0xffffffffu, d, o);
    if ((tid & 31) == 0) sh[tid >> 5] = d;
    __syncthreads();
    if (tid < 16) {
        float x = sh[tid];
#pragma unroll
        for (int o = 8; o; o >>= 1) x += __shfl_xor_sync(0x0000ffffu, x, o);
        if (tid == 0) out[0] = x * (1.0f / BB);
    }
}

extern "C" void kernel_launch(void* const* d_in, const int* in_sizes, int n_in,
                              void* d_out, int out_size) {
    (void)in_sizes; (void)n_in; (void)out_size;
    const float* em   = (const float*)d_in[0];
    const float* T    = (const float*)d_in[1];
    const float* mask = (const float*)d_in[2];
    const int*   tags = (const int*)d_in[3];
    float* out = (float*)d_out;

    prep_kernel<<<4, 512>>>(T);
    alpha_kernel<<<BB, CC>>>(em, mask);
    scores_kernel<<<BB, 256>>>(em, T, mask, tags);
    finalize_kernel<<<1, 512>>>(out);
}